// round 13
// baseline (speedup 1.0000x reference)
#include <cuda_runtime.h>
#include <cuda_bf16.h>
#include <math.h>
#include <stdint.h>

// ---------------- problem constants ----------------
#define C_     192
#define NHEAD  6
#define HID_   768
#define BATCH  32
#define NWTOT  2048
#define MROWS  100352      // NWTOT * 49
#define MBT    784         // MROWS / 128
#define NSM    148
#define GPERS  (NSM * 4)   // persistent grid

// ---------------- scratch (device globals) ----------------
__device__ __nv_bfloat16  g_qkv [(size_t)MROWS * 3 * C_];
__device__ float          g_x1  [(size_t)MROWS * C_];
__device__ __nv_bfloat16  g_xw  [(size_t)MROWS * C_];
__device__ __nv_bfloat16  g_at  [(size_t)MROWS * C_];
__device__ __nv_bfloat16  g_x2  [(size_t)MROWS * C_];
__device__ __nv_bfloat16  g_h1  [(size_t)MROWS * HID_];
__device__ __nv_bfloat16  g_wq[576 * 192];
__device__ __nv_bfloat16  g_wp[192 * 192];
__device__ __nv_bfloat16  g_w1[768 * 192];
__device__ __nv_bfloat16  g_w2[192 * 768];
__device__ __nv_bfloat16  g_battn[24 * 4096];   // [class(4) x head(6)][64x64] bias+mask (bf16)

// ---------------- helpers ----------------
__device__ __forceinline__ uint32_t smem_u32(const void* p) {
    uint32_t a;
    asm("{ .reg .u64 t; cvta.to.shared.u64 t, %1; cvt.u32.u64 %0, t; }" : "=r"(a) : "l"(p));
    return a;
}
__device__ __forceinline__ float warp_sum(float v) {
#pragma unroll
    for (int o = 16; o; o >>= 1) v += __shfl_xor_sync(0xffffffffu, v, o);
    return v;
}
__device__ __forceinline__ float gelu_exact(float x) {
    return 0.5f * x * (1.0f + erff(x * 0.70710678118654752f));
}
__device__ __forceinline__ uint32_t pack_bf2(float a, float b) {
    __nv_bfloat162 t = __floats2bfloat162_rn(a, b);
    return *(uint32_t*)&t;
}
// FMA-only exp (exp2 poly)
__device__ __forceinline__ float fast_exp(float x) {
    float t = fmaxf(x * 1.4426950408889634f, -126.0f);
    float n = floorf(t);
    float f = t - n;
    float p = 1.8775767e-3f;
    p = fmaf(p, f, 8.9893397e-3f);
    p = fmaf(p, f, 5.5804084e-2f);
    p = fmaf(p, f, 2.4013971e-1f);
    p = fmaf(p, f, 6.9314718e-1f);
    p = fmaf(p, f, 1.0f);
    return p * __int_as_float(((int)n + 127) << 23);
}

__device__ __forceinline__ void ldmat4(uint32_t* r, uint32_t addr) {
    asm volatile("ldmatrix.sync.aligned.m8n8.x4.shared.b16 {%0,%1,%2,%3}, [%4];"
        : "=r"(r[0]), "=r"(r[1]), "=r"(r[2]), "=r"(r[3]) : "r"(addr));
}
__device__ __forceinline__ void ldmat2(uint32_t* r, uint32_t addr) {
    asm volatile("ldmatrix.sync.aligned.m8n8.x2.shared.b16 {%0,%1}, [%2];"
        : "=r"(r[0]), "=r"(r[1]) : "r"(addr));
}
__device__ __forceinline__ void ldmat2t(uint32_t* r, uint32_t addr) {
    asm volatile("ldmatrix.sync.aligned.m8n8.x2.trans.shared.b16 {%0,%1}, [%2];"
        : "=r"(r[0]), "=r"(r[1]) : "r"(addr));
}
__device__ __forceinline__ void mma16816(float* d, const uint32_t* a, const uint32_t* b) {
    asm volatile("mma.sync.aligned.m16n8k16.row.col.f32.bf16.bf16.f32 "
        "{%0,%1,%2,%3}, {%4,%5,%6,%7}, {%8,%9}, {%0,%1,%2,%3};"
        : "+f"(d[0]), "+f"(d[1]), "+f"(d[2]), "+f"(d[3])
        : "r"(a[0]), "r"(a[1]), "r"(a[2]), "r"(a[3]), "r"(b[0]), "r"(b[1]));
}
#define CP16(dst, src) \
    asm volatile("cp.async.cg.shared.global [%0], [%1], 16;" :: "r"(dst), "l"(src))
#define CP_COMMIT() asm volatile("cp.async.commit_group;" ::: "memory")
#define CP_WAIT(n)  asm volatile("cp.async.wait_group %0;" :: "n"(n) : "memory")

// ---------------- all weights fp32 -> bf16, one launch ----------------
#define SEG0 110592
#define SEG1 147456
#define SEG2 294912
#define SEG3 442368
__global__ void convert_all(const float* __restrict__ qkv_w, const float* __restrict__ proj_w,
                            const float* __restrict__ fc1_w, const float* __restrict__ fc2_w,
                            __nv_bfloat16* __restrict__ wq, __nv_bfloat16* __restrict__ wp,
                            __nv_bfloat16* __restrict__ w1, __nv_bfloat16* __restrict__ w2) {
    int i = blockIdx.x * blockDim.x + threadIdx.x;
    if (i < SEG0)       wq[i]        = __float2bfloat16(qkv_w[i]);
    else if (i < SEG1)  wp[i - SEG0] = __float2bfloat16(proj_w[i - SEG0]);
    else if (i < SEG2)  w1[i - SEG1] = __float2bfloat16(fc1_w[i - SEG1]);
    else if (i < SEG3)  w2[i - SEG2] = __float2bfloat16(fc2_w[i - SEG2]);
}

// ---------------- build attention bias+mask tables (bf16) ----------------
__global__ void build_battn(const float* __restrict__ bt, __nv_bfloat16* __restrict__ battn) {
    int cls  = blockIdx.x / NHEAD;
    int head = blockIdx.x % NHEAD;
    __nv_bfloat16* T = battn + (size_t)blockIdx.x * 4096;
    for (int i = threadIdx.x; i < 4096; i += 256) {
        int r = i >> 6, c = i & 63;
        float v = -1e30f;
        if (r < 49 && c < 49) {
            int rr = ((cls & 1) ? ((r / 7 < 4) ? 1 : 2) : 0) * 3
                   + ((cls & 2) ? ((r % 7 < 4) ? 1 : 2) : 0);
            int rc = ((cls & 1) ? ((c / 7 < 4) ? 1 : 2) : 0) * 3
                   + ((cls & 2) ? ((c % 7 < 4) ? 1 : 2) : 0);
            int rel = (r / 7 - c / 7 + 6) * 13 + (r % 7 - c % 7 + 6);
            v = bt[rel * NHEAD + head] + ((rr != rc) ? -100.0f : 0.0f);
        }
        T[i] = __float2bfloat16(v);
    }
}

// ---------------- LN1 + cyclic shift + window partition -> bf16 ----------------
__global__ void ln_partition_kernel(const float* __restrict__ x,
                                    const float* __restrict__ g,
                                    const float* __restrict__ bt,
                                    __nv_bfloat16* __restrict__ o) {
    int warp = (blockIdx.x * blockDim.x + threadIdx.x) >> 5;
    int lane = threadIdx.x & 31;
    if (warp >= MROWS) return;
    int n = warp % 49;
    int window = warp / 49;
    int wi = window & 63;
    int b  = window >> 6;
    int wh = wi >> 3, ww = wi & 7;
    int h = wh * 7 + n / 7 + 3; if (h >= 56) h -= 56;
    int w = ww * 7 + n % 7 + 3; if (w >= 56) w -= 56;
    const float* xi = x + ((size_t)b * 3136 + h * 56 + w) * 192;

    float v[6]; float s1 = 0.f;
#pragma unroll
    for (int j = 0; j < 6; j++) { v[j] = xi[lane + 32 * j]; s1 += v[j]; }
    s1 = warp_sum(s1);
    float mean = s1 * (1.0f / 192.0f);
    float s2 = 0.f;
#pragma unroll
    for (int j = 0; j < 6; j++) { float d = v[j] - mean; s2 += d * d; }
    s2 = warp_sum(s2);
    float inv = rsqrtf(s2 * (1.0f / 192.0f) + 1e-5f);
    size_t base = (size_t)warp * 192;
#pragma unroll
    for (int j = 0; j < 6; j++) {
        int c = lane + 32 * j;
        o[base + c] = __float2bfloat16((v[j] - mean) * inv * g[c] + bt[c]);
    }
}

// ---------------- LN2 -> bf16 ----------------
__global__ void ln_plain_kernel(const float* __restrict__ x,
                                const float* __restrict__ g,
                                const float* __restrict__ bt,
                                __nv_bfloat16* __restrict__ o) {
    int warp = (blockIdx.x * blockDim.x + threadIdx.x) >> 5;
    int lane = threadIdx.x & 31;
    if (warp >= MROWS) return;
    const float* xi = x + (size_t)warp * 192;
    float v[6]; float s1 = 0.f;
#pragma unroll
    for (int j = 0; j < 6; j++) { v[j] = xi[lane + 32 * j]; s1 += v[j]; }
    s1 = warp_sum(s1);
    float mean = s1 * (1.0f / 192.0f);
    float s2 = 0.f;
#pragma unroll
    for (int j = 0; j < 6; j++) { float d = v[j] - mean; s2 += d * d; }
    s2 = warp_sum(s2);
    float inv = rsqrtf(s2 * (1.0f / 192.0f) + 1e-5f);
    size_t base = (size_t)warp * 192;
#pragma unroll
    for (int j = 0; j < 6; j++) {
        int c = lane + 32 * j;
        o[base + c] = __float2bfloat16((v[j] - mean) * inv * g[c] + bt[c]);
    }
}

// ---------------- attention: HMMA, 2 windows (same class) x 1 head per block ----------------
__global__ void __launch_bounds__(256)
attn_kernel(const __nv_bfloat16* __restrict__ qkv,
            const __nv_bfloat16* __restrict__ battn,
            __nv_bfloat16* __restrict__ outp) {
    __shared__ __align__(16) char sQ[2][64 * 80];
    __shared__ __align__(16) char sK[2][64 * 80];
    __shared__ __align__(16) char sV[2][64 * 80];
    __shared__ __align__(16) __nv_bfloat16 sT[4096];

    const int head = blockIdx.x % NHEAD;
    const int t    = blockIdx.x / NHEAD;
    const int qp   = t >> 6;
    const int wi   = t & 63;
    const int tid  = threadIdx.x;
    const int sub  = tid >> 7;
    const int ltid = tid & 127;
    const int wrp  = ltid >> 5;
    const int lane = tid & 31;
    const int window = 128 * qp + sub * 64 + wi;

    const __nv_bfloat16* wbase = qkv + (size_t)window * 49 * 576 + head * 32;
    for (int i = ltid; i < 588; i += 128) {
        int mat = i / 196, rem = i - mat * 196;
        int row = rem >> 2, ch = rem & 3;
        uint4 v = *(const uint4*)(wbase + (size_t)row * 576 + mat * 192 + ch * 8);
        char* dst = (mat == 0) ? sQ[sub] : (mat == 1) ? sK[sub] : sV[sub];
        *(uint4*)(dst + row * 80 + ch * 16) = v;
    }
    for (int i = ltid; i < 225; i += 128) {
        int mat = i / 75, rr = i - mat * 75;
        int row = 49 + rr / 5, ch = rr % 5;
        char* dst = (mat == 0) ? sQ[sub] : (mat == 1) ? sK[sub] : sV[sub];
        *(uint4*)(dst + row * 80 + ch * 16) = make_uint4(0, 0, 0, 0);
    }
    {
        int cls = ((wi >> 3) == 7 ? 1 : 0) + ((wi & 7) == 7 ? 2 : 0);
        const __nv_bfloat16* gT = battn + (size_t)(cls * NHEAD + head) * 4096;
        for (int i = tid; i < 512; i += 256)
            *(uint4*)(sT + i * 8) = *(const uint4*)(gT + i * 8);
    }
    __syncthreads();

    const uint32_t sQu = smem_u32(sQ[sub]), sKu = smem_u32(sK[sub]), sVu = smem_u32(sV[sub]);

    uint32_t qa[2][4];
    {
        uint32_t qaddr = sQu + (uint32_t)(16 * wrp + (lane & 15)) * 80 + ((lane >> 4) * 16);
        ldmat4(qa[0], qaddr);
        ldmat4(qa[1], qaddr + 32);
    }
    float acc[8][4];
#pragma unroll
    for (int nt = 0; nt < 8; nt++)
#pragma unroll
        for (int q = 0; q < 4; q++) acc[nt][q] = 0.f;

    const uint32_t krow = (uint32_t)(lane & 7) * 80 + ((lane & 8) ? 16 : 0);
#pragma unroll
    for (int nt = 0; nt < 8; nt++) {
#pragma unroll
        for (int kk = 0; kk < 2; kk++) {
            uint32_t b[2];
            ldmat2(b, sKu + nt * 640 + kk * 32 + krow);
            mma16816(acc[nt], qa[kk], b);
        }
    }

    const float scale = 0.17677669529663687f;
    const int tr = lane >> 2;
    const int tc = (lane & 3) * 2;
    const __nv_bfloat16* T0 = sT + (16 * wrp + tr) * 64;
    const __nv_bfloat16* T1 = T0 + 8 * 64;
#pragma unroll
    for (int nt = 0; nt < 8; nt++) {
        int c = 8 * nt + tc;
        float2 t0 = __bfloat1622float2(*(const __nv_bfloat162*)(T0 + c));
        float2 t1 = __bfloat1622float2(*(const __nv_bfloat162*)(T1 + c));
        acc[nt][0] = fmaf(acc[nt][0], scale, t0.x);
        acc[nt][1] = fmaf(acc[nt][1], scale, t0.y);
        acc[nt][2] = fmaf(acc[nt][2], scale, t1.x);
        acc[nt][3] = fmaf(acc[nt][3], scale, t1.y);
    }

    float m0 = -1e30f, m1 = -1e30f;
#pragma unroll
    for (int nt = 0; nt < 8; nt++) {
        m0 = fmaxf(m0, fmaxf(acc[nt][0], acc[nt][1]));
        m1 = fmaxf(m1, fmaxf(acc[nt][2], acc[nt][3]));
    }
    m0 = fmaxf(m0, __shfl_xor_sync(0xffffffffu, m0, 1));
    m0 = fmaxf(m0, __shfl_xor_sync(0xffffffffu, m0, 2));
    m1 = fmaxf(m1, __shfl_xor_sync(0xffffffffu, m1, 1));
    m1 = fmaxf(m1, __shfl_xor_sync(0xffffffffu, m1, 2));
    float s0 = 0.f, s1 = 0.f;
#pragma unroll
    for (int nt = 0; nt < 8; nt++) {
        acc[nt][0] = fast_exp(acc[nt][0] - m0); s0 += acc[nt][0];
        acc[nt][1] = fast_exp(acc[nt][1] - m0); s0 += acc[nt][1];
        acc[nt][2] = fast_exp(acc[nt][2] - m1); s1 += acc[nt][2];
        acc[nt][3] = fast_exp(acc[nt][3] - m1); s1 += acc[nt][3];
    }
    s0 += __shfl_xor_sync(0xffffffffu, s0, 1);
    s0 += __shfl_xor_sync(0xffffffffu, s0, 2);
    s1 += __shfl_xor_sync(0xffffffffu, s1, 1);
    s1 += __shfl_xor_sync(0xffffffffu, s1, 2);
    const float i0 = __frcp_rn(s0), i1 = __frcp_rn(s1);

    uint32_t pa[4][4];
#pragma unroll
    for (int kk = 0; kk < 4; kk++) {
        pa[kk][0] = pack_bf2(acc[2 * kk][0] * i0, acc[2 * kk][1] * i0);
        pa[kk][1] = pack_bf2(acc[2 * kk][2] * i1, acc[2 * kk][3] * i1);
        pa[kk][2] = pack_bf2(acc[2 * kk + 1][0] * i0, acc[2 * kk + 1][1] * i0);
        pa[kk][3] = pack_bf2(acc[2 * kk + 1][2] * i1, acc[2 * kk + 1][3] * i1);
    }

    float o[4][4];
#pragma unroll
    for (int nt = 0; nt < 4; nt++)
#pragma unroll
        for (int q = 0; q < 4; q++) o[nt][q] = 0.f;

    const uint32_t vrow = sVu + (uint32_t)(lane & 15) * 80;
#pragma unroll
    for (int kk = 0; kk < 4; kk++) {
#pragma unroll
        for (int nt = 0; nt < 4; nt++) {
            uint32_t b[2];
            ldmat2t(b, vrow + kk * (16 * 80) + nt * 16);
            mma16816(o[nt], pa[kk], b);
        }
    }

    const int gr0 = 16 * wrp + tr, gr1 = gr0 + 8;
    __nv_bfloat16* ob = outp + (size_t)window * 49 * 192 + head * 32;
#pragma unroll
    for (int nt = 0; nt < 4; nt++) {
        int d = 8 * nt + tc;
        if (gr0 < 49) *(uint32_t*)(ob + (size_t)gr0 * 192 + d) = pack_bf2(o[nt][0], o[nt][1]);
        if (gr1 < 49) *(uint32_t*)(ob + (size_t)gr1 * 192 + d) = pack_bf2(o[nt][2], o[nt][3]);
    }
}

// ---------------- PERSISTENT bf16 mma GEMM: BM=128, BN=64, seamless chunk ring ----------------
#define SB_OFF 16384                  // 128 rows * 128B
#define STAGE  24576                  // + 64 rows * 128B
#define SM_TOT (2 * STAGE)            // 49152

enum { EPI_QKV = 0, EPI_PROJ = 1, EPI_GELU = 2, EPI_RES = 3 };

__device__ __forceinline__ size_t proj_row(int m) {
    int n = m % 49, window = m / 49;
    int wi = window & 63, b = window >> 6;
    int wh = wi >> 3, ww = wi & 7;
    int hh = wh * 7 + n / 7 + 3; if (hh >= 56) hh -= 56;
    int wc = ww * 7 + n % 7 + 3; if (wc >= 56) wc -= 56;
    return ((size_t)b * 3136 + (size_t)hh * 56 + wc) * 192;
}

template<int EPI>
__global__ void __launch_bounds__(128, 4)
gemm_mma(const __nv_bfloat16* __restrict__ A, const __nv_bfloat16* __restrict__ W,
         const float* __restrict__ bias, float* __restrict__ Cout,
         int Nn, int Ktot, const float* __restrict__ extra,
         __nv_bfloat16* __restrict__ obf) {
    extern __shared__ __align__(16) char sm[];
    const uint32_t sb = smem_u32(sm);
    const int tid  = threadIdx.x;
    const int wid  = tid >> 5;
    const int lane = tid & 31;
    const int warpM = wid >> 1;
    const int warpN = wid & 1;

    const int rowA = warpM * 64 + (lane & 15);
    const uint32_t aBase = (uint32_t)rowA * 128;
    const int axp = (lane >> 4) ^ (rowA & 7);
    const int rowB = warpN * 32 + ((lane >> 4) & 1) * 8 + (lane & 7);
    const uint32_t bBase = SB_OFF + (uint32_t)rowB * 128;
    const int bxp = ((lane >> 3) & 1) ^ (lane & 7);

    const int NK = Ktot >> 6;                    // K / 64
    const int NT = (Nn >> 6) * MBT;              // total tiles

    // stage loader: chunk (tile t, k-chunk kc) into buffer buf
    auto stage_load = [&](int buf, int t, int kc) {
        const int mt = t % MBT, nt = t / MBT;
        const __nv_bfloat16* A_b = A + (size_t)(mt * 128) * Ktot + (kc << 6);
        const __nv_bfloat16* W_b = W + (size_t)(nt * 64) * Ktot + (kc << 6);
        uint32_t d = sb + buf * STAGE;
#pragma unroll
        for (int i = 0; i < 8; i++) {
            int idx = tid + 128 * i;
            int row = idx >> 3, ch = idx & 7;
            CP16(d + row * 128 + ((ch ^ (row & 7)) << 4), A_b + (size_t)row * Ktot + ch * 8);
        }
#pragma unroll
        for (int i = 0; i < 4; i++) {
            int idx = tid + 128 * i;
            int row = idx >> 3, ch = idx & 7;
            CP16(d + SB_OFF + row * 128 + ((ch ^ (row & 7)) << 4), W_b + (size_t)row * Ktot + ch * 8);
        }
        CP_COMMIT();
    };

    int buf = 0;
    if ((int)blockIdx.x < NT) stage_load(0, blockIdx.x, 0);

    for (int t = blockIdx.x; t < NT; t += GPERS) {
        const int mt = t % MBT, ntile = t / MBT;
        const int bm = mt * 128, bn = ntile * 64;

        float acc[4][4][4];
#pragma unroll
        for (int i = 0; i < 4; i++)
#pragma unroll
            for (int j = 0; j < 4; j++)
#pragma unroll
                for (int k = 0; k < 4; k++) acc[i][j][k] = 0.f;

        for (int k = 0; k < NK; k++) {
            CP_WAIT(0);
            __syncthreads();
            // prefetch next chunk: next k, or first chunk of next tile
            if (k + 1 < NK)            stage_load(buf ^ 1, t, k + 1);
            else if (t + GPERS < NT)   stage_load(buf ^ 1, t + GPERS, 0);

            const uint32_t soff = sb + buf * STAGE;
            const uint32_t aaddr = soff + aBase;
            const uint32_t baddr = soff + bBase;

#pragma unroll
            for (int kk = 0; kk < 4; kk++) {
                const uint32_t xa = (uint32_t)((2 * kk) ^ axp) << 4;
                const uint32_t xb = (uint32_t)((2 * kk) ^ bxp) << 4;
                uint32_t a0[4], a1[4], a2[4], a3[4];
                ldmat4(a0, aaddr + xa);
                ldmat4(a1, aaddr + 2048 + xa);
                ldmat4(a2, aaddr + 4096 + xa);
                ldmat4(a3, aaddr + 6144 + xa);
#pragma unroll
                for (int ng = 0; ng < 2; ng++) {
                    uint32_t bh[4];
                    ldmat4(bh, baddr + ng * 2048 + xb);
#pragma unroll
                    for (int q = 0; q < 2; q++) {
                        int ni = ng * 2 + q;
                        mma16816(acc[0][ni], a0, bh + 2 * q);
                        mma16816(acc[1][ni], a1, bh + 2 * q);
                        mma16816(acc[2][ni], a2, bh + 2 * q);
                        mma16816(acc[3][ni], a3, bh + 2 * q);
                    }
                }
            }
            buf ^= 1;
        }

        // ---------------- epilogue (overlaps next tile's in-flight loads) ----------------
        const int lrow = lane >> 2, lcol = (lane & 3) * 2;
#pragma unroll
        for (int mi = 0; mi < 4; mi++) {
            int m0 = bm + warpM * 64 + mi * 16 + lrow;
            int m1 = m0 + 8;
            size_t r0, r1;
            if (EPI == EPI_PROJ) { r0 = proj_row(m0); r1 = proj_row(m1); }
            else { r0 = (size_t)m0 * Nn; r1 = (size_t)m1 * Nn; }
#pragma unroll
            for (int ni = 0; ni < 4; ni++) {
                int n = bn + warpN * 32 + ni * 8 + lcol;
                float bx = bias[n], by = bias[n + 1];
                float v0x = acc[mi][ni][0] + bx, v0y = acc[mi][ni][1] + by;
                float v1x = acc[mi][ni][2] + bx, v1y = acc[mi][ni][3] + by;
                if (EPI == EPI_QKV) {
                    *(uint32_t*)(obf + r0 + n) = pack_bf2(v0x, v0y);
                    *(uint32_t*)(obf + r1 + n) = pack_bf2(v1x, v1y);
                } else if (EPI == EPI_GELU) {
                    *(uint32_t*)(obf + r0 + n) = pack_bf2(gelu_exact(v0x), gelu_exact(v0y));
                    *(uint32_t*)(obf + r1 + n) = pack_bf2(gelu_exact(v1x), gelu_exact(v1y));
                } else {
                    float2 e0 = *(const float2*)(extra + r0 + n);
                    float2 e1 = *(const float2*)(extra + r1 + n);
                    *(float2*)(Cout + r0 + n) = make_float2(v0x + e0.x, v0y + e0.y);
                    *(float2*)(Cout + r1 + n) = make_float2(v1x + e1.x, v1y + e1.y);
                }
            }
        }
    }
}

// ---------------- launch ----------------
extern "C" void kernel_launch(void* const* d_in, const int* in_sizes, int n_in,
                              void* d_out, int out_size) {
    const float* x      = (const float*)d_in[0];
    const float* g1     = (const float*)d_in[1];
    const float* b1     = (const float*)d_in[2];
    const float* qkv_w  = (const float*)d_in[3];
    const float* qkv_b  = (const float*)d_in[4];
    const float* proj_w = (const float*)d_in[5];
    const float* proj_b = (const float*)d_in[6];
    const float* bias_t = (const float*)d_in[7];
    const float* g2     = (const float*)d_in[8];
    const float* b2     = (const float*)d_in[9];
    const float* fc1_w  = (const float*)d_in[10];
    const float* fc1_b  = (const float*)d_in[11];
    const float* fc2_w  = (const float*)d_in[12];
    const float* fc2_b  = (const float*)d_in[13];
    float* out = (float*)d_out;

    float* p_x1;
    __nv_bfloat16 *p_qkv, *p_xw, *p_at, *p_x2, *p_h1, *p_wq, *p_wp, *p_w1, *p_w2, *p_battn;
    cudaGetSymbolAddress((void**)&p_qkv, g_qkv);
    cudaGetSymbolAddress((void**)&p_x1,  g_x1);
    cudaGetSymbolAddress((void**)&p_xw,  g_xw);
    cudaGetSymbolAddress((void**)&p_at,  g_at);
    cudaGetSymbolAddress((void**)&p_x2,  g_x2);
    cudaGetSymbolAddress((void**)&p_h1,  g_h1);
    cudaGetSymbolAddress((void**)&p_wq,  g_wq);
    cudaGetSymbolAddress((void**)&p_wp,  g_wp);
    cudaGetSymbolAddress((void**)&p_w1,  g_w1);
    cudaGetSymbolAddress((void**)&p_w2,  g_w2);
    cudaGetSymbolAddress((void**)&p_battn, g_battn);

    cudaFuncSetAttribute(gemm_mma<EPI_QKV>,  cudaFuncAttributeMaxDynamicSharedMemorySize, SM_TOT);
    cudaFuncSetAttribute(gemm_mma<EPI_PROJ>, cudaFuncAttributeMaxDynamicSharedMemorySize, SM_TOT);
    cudaFuncSetAttribute(gemm_mma<EPI_GELU>, cudaFuncAttributeMaxDynamicSharedMemorySize, SM_TOT);
    cudaFuncSetAttribute(gemm_mma<EPI_RES>,  cudaFuncAttributeMaxDynamicSharedMemorySize, SM_TOT);

    convert_all<<<SEG3 / 256, 256>>>(qkv_w, proj_w, fc1_w, fc2_w, p_wq, p_wp, p_w1, p_w2);
    build_battn<<<24, 256>>>(bias_t, p_battn);
    ln_partition_kernel<<<MROWS / 8, 256>>>(x, g1, b1, p_xw);
    gemm_mma<EPI_QKV><<<GPERS, 128, SM_TOT>>>(p_xw, p_wq, qkv_b, nullptr, 576, 192, nullptr, p_qkv);
    attn_kernel<<<NWTOT * NHEAD / 2, 256>>>(p_qkv, p_battn, p_at);
    gemm_mma<EPI_PROJ><<<GPERS, 128, SM_TOT>>>(p_at, p_wp, proj_b, p_x1, 192, 192, x, nullptr);
    ln_plain_kernel<<<MROWS / 8, 256>>>(p_x1, g2, b2, p_x2);
    gemm_mma<EPI_GELU><<<GPERS, 128, SM_TOT>>>(p_x2, p_w1, fc1_b, nullptr, 768, 192, nullptr, p_h1);
    gemm_mma<EPI_RES><<<GPERS, 128, SM_TOT>>>(p_h1, p_w2, fc2_b, out, 192, 768, p_x1, nullptr);
}

// round 14
// speedup vs baseline: 1.0781x; 1.0781x over previous
#include <cuda_runtime.h>
#include <cuda_bf16.h>
#include <math.h>
#include <stdint.h>

// ---------------- problem constants ----------------
#define C_     192
#define NHEAD  6
#define HID_   768
#define BATCH  32
#define NWTOT  2048
#define MROWS  100352      // NWTOT * 49

// ---------------- scratch (device globals) ----------------
__device__ __nv_bfloat16  g_qkv [(size_t)MROWS * 3 * C_];   // head-blocked: [win][head][mat][49][32]
__device__ float          g_x1  [(size_t)MROWS * C_];
__device__ __nv_bfloat16  g_xw  [(size_t)MROWS * C_];
__device__ __nv_bfloat16  g_at  [(size_t)MROWS * C_];
__device__ __nv_bfloat16  g_x2  [(size_t)MROWS * C_];
__device__ __nv_bfloat16  g_h1  [(size_t)MROWS * HID_];
__device__ __nv_bfloat16  g_wq[576 * 192];
__device__ __nv_bfloat16  g_wp[192 * 192];
__device__ __nv_bfloat16  g_w1[768 * 192];
__device__ __nv_bfloat16  g_w2[192 * 768];
__device__ __nv_bfloat16  g_battn[24 * 4096];   // [class(4) x head(6)][64x64] bias+mask (bf16)

// ---------------- helpers ----------------
__device__ __forceinline__ uint32_t smem_u32(const void* p) {
    uint32_t a;
    asm("{ .reg .u64 t; cvta.to.shared.u64 t, %1; cvt.u32.u64 %0, t; }" : "=r"(a) : "l"(p));
    return a;
}
__device__ __forceinline__ float warp_sum(float v) {
#pragma unroll
    for (int o = 16; o; o >>= 1) v += __shfl_xor_sync(0xffffffffu, v, o);
    return v;
}
__device__ __forceinline__ float gelu_exact(float x) {
    return 0.5f * x * (1.0f + erff(x * 0.70710678118654752f));
}
__device__ __forceinline__ uint32_t pack_bf2(float a, float b) {
    __nv_bfloat162 t = __floats2bfloat162_rn(a, b);
    return *(uint32_t*)&t;
}
// FMA-only exp (exp2 poly)
__device__ __forceinline__ float fast_exp(float x) {
    float t = fmaxf(x * 1.4426950408889634f, -126.0f);
    float n = floorf(t);
    float f = t - n;
    float p = 1.8775767e-3f;
    p = fmaf(p, f, 8.9893397e-3f);
    p = fmaf(p, f, 5.5804084e-2f);
    p = fmaf(p, f, 2.4013971e-1f);
    p = fmaf(p, f, 6.9314718e-1f);
    p = fmaf(p, f, 1.0f);
    return p * __int_as_float(((int)n + 127) << 23);
}

__device__ __forceinline__ void ldmat4(uint32_t* r, uint32_t addr) {
    asm volatile("ldmatrix.sync.aligned.m8n8.x4.shared.b16 {%0,%1,%2,%3}, [%4];"
        : "=r"(r[0]), "=r"(r[1]), "=r"(r[2]), "=r"(r[3]) : "r"(addr));
}
__device__ __forceinline__ void ldmat2(uint32_t* r, uint32_t addr) {
    asm volatile("ldmatrix.sync.aligned.m8n8.x2.shared.b16 {%0,%1}, [%2];"
        : "=r"(r[0]), "=r"(r[1]) : "r"(addr));
}
__device__ __forceinline__ void ldmat2t(uint32_t* r, uint32_t addr) {
    asm volatile("ldmatrix.sync.aligned.m8n8.x2.trans.shared.b16 {%0,%1}, [%2];"
        : "=r"(r[0]), "=r"(r[1]) : "r"(addr));
}
__device__ __forceinline__ void mma16816(float* d, const uint32_t* a, const uint32_t* b) {
    asm volatile("mma.sync.aligned.m16n8k16.row.col.f32.bf16.bf16.f32 "
        "{%0,%1,%2,%3}, {%4,%5,%6,%7}, {%8,%9}, {%0,%1,%2,%3};"
        : "+f"(d[0]), "+f"(d[1]), "+f"(d[2]), "+f"(d[3])
        : "r"(a[0]), "r"(a[1]), "r"(a[2]), "r"(a[3]), "r"(b[0]), "r"(b[1]));
}
#define CP16(dst, src) \
    asm volatile("cp.async.cg.shared.global [%0], [%1], 16;" :: "r"(dst), "l"(src))
#define CP_COMMIT() asm volatile("cp.async.commit_group;" ::: "memory")
#define CP_WAIT(n)  asm volatile("cp.async.wait_group %0;" :: "n"(n) : "memory")

// ---------------- all weights fp32 -> bf16, one launch ----------------
#define SEG0 110592
#define SEG1 147456
#define SEG2 294912
#define SEG3 442368
__global__ void convert_all(const float* __restrict__ qkv_w, const float* __restrict__ proj_w,
                            const float* __restrict__ fc1_w, const float* __restrict__ fc2_w,
                            __nv_bfloat16* __restrict__ wq, __nv_bfloat16* __restrict__ wp,
                            __nv_bfloat16* __restrict__ w1, __nv_bfloat16* __restrict__ w2) {
    int i = blockIdx.x * blockDim.x + threadIdx.x;
    if (i < SEG0)       wq[i]        = __float2bfloat16(qkv_w[i]);
    else if (i < SEG1)  wp[i - SEG0] = __float2bfloat16(proj_w[i - SEG0]);
    else if (i < SEG2)  w1[i - SEG1] = __float2bfloat16(fc1_w[i - SEG1]);
    else if (i < SEG3)  w2[i - SEG2] = __float2bfloat16(fc2_w[i - SEG2]);
}

// ---------------- build attention bias+mask tables (bf16) ----------------
__global__ void build_battn(const float* __restrict__ bt, __nv_bfloat16* __restrict__ battn) {
    int cls  = blockIdx.x / NHEAD;
    int head = blockIdx.x % NHEAD;
    __nv_bfloat16* T = battn + (size_t)blockIdx.x * 4096;
    for (int i = threadIdx.x; i < 4096; i += 256) {
        int r = i >> 6, c = i & 63;
        float v = -1e30f;
        if (r < 49 && c < 49) {
            int rr = ((cls & 1) ? ((r / 7 < 4) ? 1 : 2) : 0) * 3
                   + ((cls & 2) ? ((r % 7 < 4) ? 1 : 2) : 0);
            int rc = ((cls & 1) ? ((c / 7 < 4) ? 1 : 2) : 0) * 3
                   + ((cls & 2) ? ((c % 7 < 4) ? 1 : 2) : 0);
            int rel = (r / 7 - c / 7 + 6) * 13 + (r % 7 - c % 7 + 6);
            v = bt[rel * NHEAD + head] + ((rr != rc) ? -100.0f : 0.0f);
        }
        T[i] = __float2bfloat16(v);
    }
}

// ---------------- LN1 + cyclic shift + window partition -> bf16 ----------------
__global__ void ln_partition_kernel(const float* __restrict__ x,
                                    const float* __restrict__ g,
                                    const float* __restrict__ bt,
                                    __nv_bfloat16* __restrict__ o) {
    int warp = (blockIdx.x * blockDim.x + threadIdx.x) >> 5;
    int lane = threadIdx.x & 31;
    if (warp >= MROWS) return;
    int n = warp % 49;
    int window = warp / 49;
    int wi = window & 63;
    int b  = window >> 6;
    int wh = wi >> 3, ww = wi & 7;
    int h = wh * 7 + n / 7 + 3; if (h >= 56) h -= 56;
    int w = ww * 7 + n % 7 + 3; if (w >= 56) w -= 56;
    const float* xi = x + ((size_t)b * 3136 + h * 56 + w) * 192;

    float v[6]; float s1 = 0.f;
#pragma unroll
    for (int j = 0; j < 6; j++) { v[j] = xi[lane + 32 * j]; s1 += v[j]; }
    s1 = warp_sum(s1);
    float mean = s1 * (1.0f / 192.0f);
    float s2 = 0.f;
#pragma unroll
    for (int j = 0; j < 6; j++) { float d = v[j] - mean; s2 += d * d; }
    s2 = warp_sum(s2);
    float inv = rsqrtf(s2 * (1.0f / 192.0f) + 1e-5f);
    size_t base = (size_t)warp * 192;
#pragma unroll
    for (int j = 0; j < 6; j++) {
        int c = lane + 32 * j;
        o[base + c] = __float2bfloat16((v[j] - mean) * inv * g[c] + bt[c]);
    }
}

// ---------------- LN2 -> bf16 ----------------
__global__ void ln_plain_kernel(const float* __restrict__ x,
                                const float* __restrict__ g,
                                const float* __restrict__ bt,
                                __nv_bfloat16* __restrict__ o) {
    int warp = (blockIdx.x * blockDim.x + threadIdx.x) >> 5;
    int lane = threadIdx.x & 31;
    if (warp >= MROWS) return;
    const float* xi = x + (size_t)warp * 192;
    float v[6]; float s1 = 0.f;
#pragma unroll
    for (int j = 0; j < 6; j++) { v[j] = xi[lane + 32 * j]; s1 += v[j]; }
    s1 = warp_sum(s1);
    float mean = s1 * (1.0f / 192.0f);
    float s2 = 0.f;
#pragma unroll
    for (int j = 0; j < 6; j++) { float d = v[j] - mean; s2 += d * d; }
    s2 = warp_sum(s2);
    float inv = rsqrtf(s2 * (1.0f / 192.0f) + 1e-5f);
    size_t base = (size_t)warp * 192;
#pragma unroll
    for (int j = 0; j < 6; j++) {
        int c = lane + 32 * j;
        o[base + c] = __float2bfloat16((v[j] - mean) * inv * g[c] + bt[c]);
    }
}

// ---------------- attention: HMMA, 2 windows (same class) x 1 head per block ----------------
// QKV is head-blocked: base = (window*6 + head)*4704; q/k/v at +0/+1568/+3136 (fully contiguous)
__global__ void __launch_bounds__(256)
attn_kernel(const __nv_bfloat16* __restrict__ qkv,
            const __nv_bfloat16* __restrict__ battn,
            __nv_bfloat16* __restrict__ outp) {
    __shared__ __align__(16) char sQ[2][64 * 80];
    __shared__ __align__(16) char sK[2][64 * 80];
    __shared__ __align__(16) char sV[2][64 * 80];
    __shared__ __align__(16) __nv_bfloat16 sT[4096];

    const int head = blockIdx.x % NHEAD;
    const int t    = blockIdx.x / NHEAD;
    const int qp   = t >> 6;
    const int wi   = t & 63;
    const int tid  = threadIdx.x;
    const int sub  = tid >> 7;
    const int ltid = tid & 127;
    const int wrp  = ltid >> 5;
    const int lane = tid & 31;
    const int window = 128 * qp + sub * 64 + wi;

    // ---- stage QKV: perfectly coalesced contiguous reads ----
    const __nv_bfloat16* wbase = qkv + (size_t)(window * 6 + head) * 4704;
    for (int i = ltid; i < 588; i += 128) {
        uint4 v = *(const uint4*)(wbase + i * 8);
        int mat = i / 196, idx = i - mat * 196;
        int row = idx >> 2, ch = idx & 3;
        char* dst = (mat == 0) ? sQ[sub] : (mat == 1) ? sK[sub] : sV[sub];
        *(uint4*)(dst + row * 80 + ch * 16) = v;
    }
    for (int i = ltid; i < 225; i += 128) {
        int mat = i / 75, rr = i - mat * 75;
        int row = 49 + rr / 5, ch = rr % 5;
        char* dst = (mat == 0) ? sQ[sub] : (mat == 1) ? sK[sub] : sV[sub];
        *(uint4*)(dst + row * 80 + ch * 16) = make_uint4(0, 0, 0, 0);
    }
    {
        int cls = ((wi >> 3) == 7 ? 1 : 0) + ((wi & 7) == 7 ? 2 : 0);
        const __nv_bfloat16* gT = battn + (size_t)(cls * NHEAD + head) * 4096;
        for (int i = tid; i < 512; i += 256)
            *(uint4*)(sT + i * 8) = *(const uint4*)(gT + i * 8);
    }
    __syncthreads();

    const uint32_t sQu = smem_u32(sQ[sub]), sKu = smem_u32(sK[sub]), sVu = smem_u32(sV[sub]);

    uint32_t qa[2][4];
    {
        uint32_t qaddr = sQu + (uint32_t)(16 * wrp + (lane & 15)) * 80 + ((lane >> 4) * 16);
        ldmat4(qa[0], qaddr);
        ldmat4(qa[1], qaddr + 32);
    }
    float acc[8][4];
#pragma unroll
    for (int nt = 0; nt < 8; nt++)
#pragma unroll
        for (int q = 0; q < 4; q++) acc[nt][q] = 0.f;

    const uint32_t krow = (uint32_t)(lane & 7) * 80 + ((lane & 8) ? 16 : 0);
#pragma unroll
    for (int nt = 0; nt < 8; nt++) {
#pragma unroll
        for (int kk = 0; kk < 2; kk++) {
            uint32_t b[2];
            ldmat2(b, sKu + nt * 640 + kk * 32 + krow);
            mma16816(acc[nt], qa[kk], b);
        }
    }

    const float scale = 0.17677669529663687f;
    const int tr = lane >> 2;
    const int tc = (lane & 3) * 2;
    const __nv_bfloat16* T0 = sT + (16 * wrp + tr) * 64;
    const __nv_bfloat16* T1 = T0 + 8 * 64;
#pragma unroll
    for (int nt = 0; nt < 8; nt++) {
        int c = 8 * nt + tc;
        float2 t0 = __bfloat1622float2(*(const __nv_bfloat162*)(T0 + c));
        float2 t1 = __bfloat1622float2(*(const __nv_bfloat162*)(T1 + c));
        acc[nt][0] = fmaf(acc[nt][0], scale, t0.x);
        acc[nt][1] = fmaf(acc[nt][1], scale, t0.y);
        acc[nt][2] = fmaf(acc[nt][2], scale, t1.x);
        acc[nt][3] = fmaf(acc[nt][3], scale, t1.y);
    }

    float m0 = -1e30f, m1 = -1e30f;
#pragma unroll
    for (int nt = 0; nt < 8; nt++) {
        m0 = fmaxf(m0, fmaxf(acc[nt][0], acc[nt][1]));
        m1 = fmaxf(m1, fmaxf(acc[nt][2], acc[nt][3]));
    }
    m0 = fmaxf(m0, __shfl_xor_sync(0xffffffffu, m0, 1));
    m0 = fmaxf(m0, __shfl_xor_sync(0xffffffffu, m0, 2));
    m1 = fmaxf(m1, __shfl_xor_sync(0xffffffffu, m1, 1));
    m1 = fmaxf(m1, __shfl_xor_sync(0xffffffffu, m1, 2));
    float s0 = 0.f, s1 = 0.f;
#pragma unroll
    for (int nt = 0; nt < 8; nt++) {
        acc[nt][0] = fast_exp(acc[nt][0] - m0); s0 += acc[nt][0];
        acc[nt][1] = fast_exp(acc[nt][1] - m0); s0 += acc[nt][1];
        acc[nt][2] = fast_exp(acc[nt][2] - m1); s1 += acc[nt][2];
        acc[nt][3] = fast_exp(acc[nt][3] - m1); s1 += acc[nt][3];
    }
    s0 += __shfl_xor_sync(0xffffffffu, s0, 1);
    s0 += __shfl_xor_sync(0xffffffffu, s0, 2);
    s1 += __shfl_xor_sync(0xffffffffu, s1, 1);
    s1 += __shfl_xor_sync(0xffffffffu, s1, 2);
    const float i0 = __frcp_rn(s0), i1 = __frcp_rn(s1);

    uint32_t pa[4][4];
#pragma unroll
    for (int kk = 0; kk < 4; kk++) {
        pa[kk][0] = pack_bf2(acc[2 * kk][0] * i0, acc[2 * kk][1] * i0);
        pa[kk][1] = pack_bf2(acc[2 * kk][2] * i1, acc[2 * kk][3] * i1);
        pa[kk][2] = pack_bf2(acc[2 * kk + 1][0] * i0, acc[2 * kk + 1][1] * i0);
        pa[kk][3] = pack_bf2(acc[2 * kk + 1][2] * i1, acc[2 * kk + 1][3] * i1);
    }

    float o[4][4];
#pragma unroll
    for (int nt = 0; nt < 4; nt++)
#pragma unroll
        for (int q = 0; q < 4; q++) o[nt][q] = 0.f;

    const uint32_t vrow = sVu + (uint32_t)(lane & 15) * 80;
#pragma unroll
    for (int kk = 0; kk < 4; kk++) {
#pragma unroll
        for (int nt = 0; nt < 4; nt++) {
            uint32_t b[2];
            ldmat2t(b, vrow + kk * (16 * 80) + nt * 16);
            mma16816(o[nt], pa[kk], b);
        }
    }

    const int gr0 = 16 * wrp + tr, gr1 = gr0 + 8;
    __nv_bfloat16* ob = outp + (size_t)window * 49 * 192 + head * 32;
#pragma unroll
    for (int nt = 0; nt < 4; nt++) {
        int d = 8 * nt + tc;
        if (gr0 < 49) *(uint32_t*)(ob + (size_t)gr0 * 192 + d) = pack_bf2(o[nt][0], o[nt][1]);
        if (gr1 < 49) *(uint32_t*)(ob + (size_t)gr1 * 192 + d) = pack_bf2(o[nt][2], o[nt][3]);
    }
}

// ---------------- bf16 mma GEMM: BM=128, BN=64, 4 warps, 2-stage, single sync/iter ----------------
#define SB_OFF 16384                  // 128 rows * 128B
#define STAGE  24576                  // + 64 rows * 128B
#define SM_TOT (2 * STAGE)            // 49152

enum { EPI_QKV = 0, EPI_PROJ = 1, EPI_GELU = 2, EPI_RES = 3 };

__device__ __forceinline__ size_t proj_row(int m) {
    int n = m % 49, window = m / 49;
    int wi = window & 63, b = window >> 6;
    int wh = wi >> 3, ww = wi & 7;
    int hh = wh * 7 + n / 7 + 3; if (hh >= 56) hh -= 56;
    int wc = ww * 7 + n % 7 + 3; if (wc >= 56) wc -= 56;
    return ((size_t)b * 3136 + (size_t)hh * 56 + wc) * 192;
}

template<int EPI>
__global__ void __launch_bounds__(128, 4)
gemm_mma(const __nv_bfloat16* __restrict__ A, const __nv_bfloat16* __restrict__ W,
         const float* __restrict__ bias, float* __restrict__ Cout,
         int Nn, int Ktot, const float* __restrict__ extra,
         __nv_bfloat16* __restrict__ obf) {
    extern __shared__ __align__(16) char sm[];
    const uint32_t sb = smem_u32(sm);
    const int tid  = threadIdx.x;
    const int wid  = tid >> 5;
    const int lane = tid & 31;
    const int warpM = wid >> 1;
    const int warpN = wid & 1;
    const int bm = blockIdx.y * 128;
    const int bn = blockIdx.x * 64;

    const __nv_bfloat16* A_b = A + (size_t)bm * Ktot;
    const __nv_bfloat16* W_b = W + (size_t)bn * Ktot;

    const int rowA = warpM * 64 + (lane & 15);
    const uint32_t aBase = (uint32_t)rowA * 128;
    const int axp = (lane >> 4) ^ (rowA & 7);
    const int rowB = warpN * 32 + ((lane >> 4) & 1) * 8 + (lane & 7);
    const uint32_t bBase = SB_OFF + (uint32_t)rowB * 128;
    const int bxp = ((lane >> 3) & 1) ^ (lane & 7);

    float acc[4][4][4];
#pragma unroll
    for (int i = 0; i < 4; i++)
#pragma unroll
        for (int j = 0; j < 4; j++)
#pragma unroll
            for (int k = 0; k < 4; k++) acc[i][j][k] = 0.f;

    const int NK = Ktot >> 6;   // K / 64

    auto stage_load = [&](int buf, int k0) {
        uint32_t d = sb + buf * STAGE;
#pragma unroll
        for (int i = 0; i < 8; i++) {
            int idx = tid + 128 * i;
            int row = idx >> 3, ch = idx & 7;
            CP16(d + row * 128 + ((ch ^ (row & 7)) << 4), A_b + (size_t)row * Ktot + k0 + ch * 8);
        }
#pragma unroll
        for (int i = 0; i < 4; i++) {
            int idx = tid + 128 * i;
            int row = idx >> 3, ch = idx & 7;
            CP16(d + SB_OFF + row * 128 + ((ch ^ (row & 7)) << 4), W_b + (size_t)row * Ktot + k0 + ch * 8);
        }
        CP_COMMIT();
    };

    stage_load(0, 0);

    for (int k = 0; k < NK; k++) {
        CP_WAIT(0);
        __syncthreads();
        if (k + 1 < NK) stage_load((k + 1) & 1, (k + 1) << 6);

        const uint32_t soff = sb + (k & 1) * STAGE;
        const uint32_t aaddr = soff + aBase;
        const uint32_t baddr = soff + bBase;

#pragma unroll
        for (int kk = 0; kk < 4; kk++) {
            const uint32_t xa = (uint32_t)((2 * kk) ^ axp) << 4;
            const uint32_t xb = (uint32_t)((2 * kk) ^ bxp) << 4;
            uint32_t a0[4], a1[4], a2[4], a3[4];
            ldmat4(a0, aaddr + xa);
            ldmat4(a1, aaddr + 2048 + xa);
            ldmat4(a2, aaddr + 4096 + xa);
            ldmat4(a3, aaddr + 6144 + xa);
#pragma unroll
            for (int ng = 0; ng < 2; ng++) {
                uint32_t bh[4];
                ldmat4(bh, baddr + ng * 2048 + xb);
#pragma unroll
                for (int q = 0; q < 2; q++) {
                    int ni = ng * 2 + q;
                    mma16816(acc[0][ni], a0, bh + 2 * q);
                    mma16816(acc[1][ni], a1, bh + 2 * q);
                    mma16816(acc[2][ni], a2, bh + 2 * q);
                    mma16816(acc[3][ni], a3, bh + 2 * q);
                }
            }
        }
    }

    // ---------------- epilogue ----------------
    const int lrow = lane >> 2, lcol = (lane & 3) * 2;
    // EPI_QKV: head-blocked output; all 16 (mi,ni) values of a thread share (mat, head)
    int matb = 0, headb = 0;
    if (EPI == EPI_QKV) {
        int nb = bn + warpN * 32;
        matb = nb / 192;
        headb = (nb % 192) / 32;
    }
#pragma unroll
    for (int mi = 0; mi < 4; mi++) {
        int m0 = bm + warpM * 64 + mi * 16 + lrow;
        int m1 = m0 + 8;
        size_t r0, r1;
        if (EPI == EPI_PROJ) { r0 = proj_row(m0); r1 = proj_row(m1); }
        else if (EPI == EPI_QKV) {
            int w0 = m0 / 49, rr0 = m0 - w0 * 49;
            int w1 = m1 / 49, rr1 = m1 - w1 * 49;
            r0 = ((size_t)(w0 * 6 + headb) * 3 + matb) * 1568 + rr0 * 32;
            r1 = ((size_t)(w1 * 6 + headb) * 3 + matb) * 1568 + rr1 * 32;
        }
        else { r0 = (size_t)m0 * Nn; r1 = (size_t)m1 * Nn; }
#pragma unroll
        for (int ni = 0; ni < 4; ni++) {
            int n = bn + warpN * 32 + ni * 8 + lcol;
            float bx = bias[n], by = bias[n + 1];
            float v0x = acc[mi][ni][0] + bx, v0y = acc[mi][ni][1] + by;
            float v1x = acc[mi][ni][2] + bx, v1y = acc[mi][ni][3] + by;
            if (EPI == EPI_QKV) {
                int d = ni * 8 + lcol;
                *(uint32_t*)(obf + r0 + d) = pack_bf2(v0x, v0y);
                *(uint32_t*)(obf + r1 + d) = pack_bf2(v1x, v1y);
            } else if (EPI == EPI_GELU) {
                *(uint32_t*)(obf + r0 + n) = pack_bf2(gelu_exact(v0x), gelu_exact(v0y));
                *(uint32_t*)(obf + r1 + n) = pack_bf2(gelu_exact(v1x), gelu_exact(v1y));
            } else {
                float2 e0 = *(const float2*)(extra + r0 + n);
                float2 e1 = *(const float2*)(extra + r1 + n);
                *(float2*)(Cout + r0 + n) = make_float2(v0x + e0.x, v0y + e0.y);
                *(float2*)(Cout + r1 + n) = make_float2(v1x + e1.x, v1y + e1.y);
            }
        }
    }
}

// ---------------- launch ----------------
extern "C" void kernel_launch(void* const* d_in, const int* in_sizes, int n_in,
                              void* d_out, int out_size) {
    const float* x      = (const float*)d_in[0];
    const float* g1     = (const float*)d_in[1];
    const float* b1     = (const float*)d_in[2];
    const float* qkv_w  = (const float*)d_in[3];
    const float* qkv_b  = (const float*)d_in[4];
    const float* proj_w = (const float*)d_in[5];
    const float* proj_b = (const float*)d_in[6];
    const float* bias_t = (const float*)d_in[7];
    const float* g2     = (const float*)d_in[8];
    const float* b2     = (const float*)d_in[9];
    const float* fc1_w  = (const float*)d_in[10];
    const float* fc1_b  = (const float*)d_in[11];
    const float* fc2_w  = (const float*)d_in[12];
    const float* fc2_b  = (const float*)d_in[13];
    float* out = (float*)d_out;

    float* p_x1;
    __nv_bfloat16 *p_qkv, *p_xw, *p_at, *p_x2, *p_h1, *p_wq, *p_wp, *p_w1, *p_w2, *p_battn;
    cudaGetSymbolAddress((void**)&p_qkv, g_qkv);
    cudaGetSymbolAddress((void**)&p_x1,  g_x1);
    cudaGetSymbolAddress((void**)&p_xw,  g_xw);
    cudaGetSymbolAddress((void**)&p_at,  g_at);
    cudaGetSymbolAddress((void**)&p_x2,  g_x2);
    cudaGetSymbolAddress((void**)&p_h1,  g_h1);
    cudaGetSymbolAddress((void**)&p_wq,  g_wq);
    cudaGetSymbolAddress((void**)&p_wp,  g_wp);
    cudaGetSymbolAddress((void**)&p_w1,  g_w1);
    cudaGetSymbolAddress((void**)&p_w2,  g_w2);
    cudaGetSymbolAddress((void**)&p_battn, g_battn);

    cudaFuncSetAttribute(gemm_mma<EPI_QKV>,  cudaFuncAttributeMaxDynamicSharedMemorySize, SM_TOT);
    cudaFuncSetAttribute(gemm_mma<EPI_PROJ>, cudaFuncAttributeMaxDynamicSharedMemorySize, SM_TOT);
    cudaFuncSetAttribute(gemm_mma<EPI_GELU>, cudaFuncAttributeMaxDynamicSharedMemorySize, SM_TOT);
    cudaFuncSetAttribute(gemm_mma<EPI_RES>,  cudaFuncAttributeMaxDynamicSharedMemorySize, SM_TOT);

    const int MB = MROWS / 128;  // 784

    convert_all<<<SEG3 / 256, 256>>>(qkv_w, proj_w, fc1_w, fc2_w, p_wq, p_wp, p_w1, p_w2);
    build_battn<<<24, 256>>>(bias_t, p_battn);
    ln_partition_kernel<<<MROWS / 8, 256>>>(x, g1, b1, p_xw);
    gemm_mma<EPI_QKV><<<dim3(576 / 64, MB), 128, SM_TOT>>>(p_xw, p_wq, qkv_b, nullptr, 576, 192, nullptr, p_qkv);
    attn_kernel<<<NWTOT * NHEAD / 2, 256>>>(p_qkv, p_battn, p_at);
    gemm_mma<EPI_PROJ><<<dim3(192 / 64, MB), 128, SM_TOT>>>(p_at, p_wp, proj_b, p_x1, 192, 192, x, nullptr);
    ln_plain_kernel<<<MROWS / 8, 256>>>(p_x1, g2, b2, p_x2);
    gemm_mma<EPI_GELU><<<dim3(768 / 64, MB), 128, SM_TOT>>>(p_x2, p_w1, fc1_b, nullptr, 768, 192, nullptr, p_h1);
    gemm_mma<EPI_RES><<<dim3(192 / 64, MB), 128, SM_TOT>>>(p_h1, p_w2, fc2_b, out, 192, 768, p_x1, nullptr);
}